// round 1
// baseline (speedup 1.0000x reference)
#include <cuda_runtime.h>

#define EDGES 625000
#define DIM   128
#define BE    64     // edges per block
#define NT    256    // threads per block

// Thread microtile: 4 edge-rows x 8 output-cols.
// trow = tid>>4 (16 groups of 4 rows = 64 rows), tcol = tid&15 (16 groups of 8 cols = 128 cols)

__global__ __launch_bounds__(NT) void edge_mlp_kernel(
    const float* __restrict__ node_attr,   // [50000,128]
    const void*  __restrict__ eidx_raw,    // [2,E] int32 or int64 (runtime-detected)
    const float* __restrict__ edge_attr,   // [E,128]
    const float* __restrict__ W1,          // [384,128]
    const float* __restrict__ b1,          // [128]
    const float* __restrict__ W2,          // [128,128]
    const float* __restrict__ b2,          // [128]
    const float* __restrict__ gamma_,      // [128]
    const float* __restrict__ beta_,       // [128]
    float* __restrict__ out)               // [E,128]
{
    __shared__ int   sSend[BE];
    __shared__ int   sRecv[BE];
    __shared__ float sA[BE][16];       // activation k-tile (gathered)
    __shared__ float sW[16][DIM];      // weight k-tile
    __shared__ float sH[BE][DIM];      // hidden / output staging

    const int tid  = threadIdx.x;
    const int e0   = blockIdx.x * BE;
    const int trow = tid >> 4;         // 0..15
    const int tcol = tid & 15;         // 0..15

    // ---- index dtype detection: indices < 50000, so int64 => every odd
    // 32-bit word is zero. Sample 16 odd words.
    const int* raw32 = (const int*)eidx_raw;
    bool is64 = true;
    #pragma unroll
    for (int i = 0; i < 16; i++) is64 &= (raw32[2 * i + 1] == 0);

    if (tid < BE) {
        int eg = e0 + tid; if (eg >= EDGES) eg = EDGES - 1;
        int s, r;
        if (is64) {
            const long long* p = (const long long*)eidx_raw;
            s = (int)p[eg]; r = (int)p[EDGES + eg];
        } else {
            s = raw32[eg]; r = raw32[EDGES + eg];
        }
        sSend[tid] = s; sRecv[tid] = r;
    }

    // =========================== GEMM1: [64,384] @ [384,128] ================
    float acc[4][8];
    #pragma unroll
    for (int i = 0; i < 4; i++)
        #pragma unroll
        for (int j = 0; j < 8; j++) acc[i][j] = 0.0f;

    const int eld  = tid >> 2;     // 0..63  : edge row this thread loads
    const int part = tid & 3;      // 0..3   : which 4-float chunk of the 16-k tile
    int egld = e0 + eld; if (egld >= EDGES) egld = EDGES - 1;

    #pragma unroll 1
    for (int t = 0; t < 24; t++) {
        __syncthreads();   // previous-tile consumers done before overwrite

        // load weight k-tile: W1 rows [t*16, t*16+16), 512 float4s
        #pragma unroll
        for (int it = 0; it < 2; it++) {
            int f4 = tid + it * NT;          // 0..511
            int kk = f4 >> 5;                // 0..15
            int c4 = f4 & 31;                // 0..31
            *(float4*)&sW[kk][c4 * 4] =
                ((const float4*)(W1 + (size_t)(t * 16 + kk) * DIM))[c4];
        }

        // load activation k-tile (gathered): 4 threads per edge, float4 each
        {
            const float* src;
            if (t < 8)       src = node_attr + (size_t)sSend[eld] * DIM + t * 16        + part * 4;
            else if (t < 16) src = node_attr + (size_t)sRecv[eld] * DIM + (t - 8) * 16  + part * 4;
            else             src = edge_attr + (size_t)egld       * DIM + (t - 16) * 16 + part * 4;
            float4 v = *(const float4*)src;
            sA[eld][part * 4 + 0] = v.x;
            sA[eld][part * 4 + 1] = v.y;
            sA[eld][part * 4 + 2] = v.z;
            sA[eld][part * 4 + 3] = v.w;
        }
        __syncthreads();

        #pragma unroll
        for (int kk = 0; kk < 16; kk++) {
            float a0 = sA[trow * 4 + 0][kk];
            float a1 = sA[trow * 4 + 1][kk];
            float a2 = sA[trow * 4 + 2][kk];
            float a3 = sA[trow * 4 + 3][kk];
            float4 w0 = *(float4*)&sW[kk][tcol * 8];
            float4 w1 = *(float4*)&sW[kk][tcol * 8 + 4];
            const float w[8] = {w0.x, w0.y, w0.z, w0.w, w1.x, w1.y, w1.z, w1.w};
            #pragma unroll
            for (int j = 0; j < 8; j++) {
                acc[0][j] = fmaf(a0, w[j], acc[0][j]);
                acc[1][j] = fmaf(a1, w[j], acc[1][j]);
                acc[2][j] = fmaf(a2, w[j], acc[2][j]);
                acc[3][j] = fmaf(a3, w[j], acc[3][j]);
            }
        }
    }

    // bias + ReLU -> sH
    __syncthreads();
    {
        float4 bb0 = *(const float4*)(b1 + tcol * 8);
        float4 bb1 = *(const float4*)(b1 + tcol * 8 + 4);
        const float bb[8] = {bb0.x, bb0.y, bb0.z, bb0.w, bb1.x, bb1.y, bb1.z, bb1.w};
        #pragma unroll
        for (int i = 0; i < 4; i++) {
            float4 v0, v1;
            v0.x = fmaxf(acc[i][0] + bb[0], 0.0f);
            v0.y = fmaxf(acc[i][1] + bb[1], 0.0f);
            v0.z = fmaxf(acc[i][2] + bb[2], 0.0f);
            v0.w = fmaxf(acc[i][3] + bb[3], 0.0f);
            v1.x = fmaxf(acc[i][4] + bb[4], 0.0f);
            v1.y = fmaxf(acc[i][5] + bb[5], 0.0f);
            v1.z = fmaxf(acc[i][6] + bb[6], 0.0f);
            v1.w = fmaxf(acc[i][7] + bb[7], 0.0f);
            *(float4*)&sH[trow * 4 + i][tcol * 8]     = v0;
            *(float4*)&sH[trow * 4 + i][tcol * 8 + 4] = v1;
        }
    }
    __syncthreads();

    // =========================== GEMM2: [64,128] @ [128,128] ================
    float acc2[4][8];
    #pragma unroll
    for (int i = 0; i < 4; i++)
        #pragma unroll
        for (int j = 0; j < 8; j++) acc2[i][j] = 0.0f;

    #pragma unroll 1
    for (int t = 0; t < 8; t++) {
        __syncthreads();
        #pragma unroll
        for (int it = 0; it < 2; it++) {
            int f4 = tid + it * NT;
            int kk = f4 >> 5;
            int c4 = f4 & 31;
            *(float4*)&sW[kk][c4 * 4] =
                ((const float4*)(W2 + (size_t)(t * 16 + kk) * DIM))[c4];
        }
        __syncthreads();

        #pragma unroll
        for (int kk = 0; kk < 16; kk++) {
            int kg = t * 16 + kk;
            float a0 = sH[trow * 4 + 0][kg];
            float a1 = sH[trow * 4 + 1][kg];
            float a2 = sH[trow * 4 + 2][kg];
            float a3 = sH[trow * 4 + 3][kg];
            float4 w0 = *(float4*)&sW[kk][tcol * 8];
            float4 w1 = *(float4*)&sW[kk][tcol * 8 + 4];
            const float w[8] = {w0.x, w0.y, w0.z, w0.w, w1.x, w1.y, w1.z, w1.w};
            #pragma unroll
            for (int j = 0; j < 8; j++) {
                acc2[0][j] = fmaf(a0, w[j], acc2[0][j]);
                acc2[1][j] = fmaf(a1, w[j], acc2[1][j]);
                acc2[2][j] = fmaf(a2, w[j], acc2[2][j]);
                acc2[3][j] = fmaf(a3, w[j], acc2[3][j]);
            }
        }
    }

    // bias2 -> sH (overwrite after all reads done)
    __syncthreads();
    {
        float4 bb0 = *(const float4*)(b2 + tcol * 8);
        float4 bb1 = *(const float4*)(b2 + tcol * 8 + 4);
        const float bb[8] = {bb0.x, bb0.y, bb0.z, bb0.w, bb1.x, bb1.y, bb1.z, bb1.w};
        #pragma unroll
        for (int i = 0; i < 4; i++) {
            float4 v0, v1;
            v0.x = acc2[i][0] + bb[0];
            v0.y = acc2[i][1] + bb[1];
            v0.z = acc2[i][2] + bb[2];
            v0.w = acc2[i][3] + bb[3];
            v1.x = acc2[i][4] + bb[4];
            v1.y = acc2[i][5] + bb[5];
            v1.z = acc2[i][6] + bb[6];
            v1.w = acc2[i][7] + bb[7];
            *(float4*)&sH[trow * 4 + i][tcol * 8]     = v0;
            *(float4*)&sH[trow * 4 + i][tcol * 8 + 4] = v1;
        }
    }
    __syncthreads();

    // =========================== LayerNorm + store ===========================
    {
        const int lane = tid & 31;
        const int warp = tid >> 5;
        float g0 = gamma_[lane],      g1 = gamma_[lane + 32],
              g2 = gamma_[lane + 64], g3 = gamma_[lane + 96];
        float be0 = beta_[lane],      be1 = beta_[lane + 32],
              be2 = beta_[lane + 64], be3 = beta_[lane + 96];

        #pragma unroll 1
        for (int r = warp; r < BE; r += 8) {
            float v0 = sH[r][lane];
            float v1 = sH[r][lane + 32];
            float v2 = sH[r][lane + 64];
            float v3 = sH[r][lane + 96];
            float sum = v0 + v1 + v2 + v3;
            float sq  = v0 * v0 + v1 * v1 + v2 * v2 + v3 * v3;
            #pragma unroll
            for (int off = 16; off > 0; off >>= 1) {
                sum += __shfl_xor_sync(0xffffffffu, sum, off);
                sq  += __shfl_xor_sync(0xffffffffu, sq,  off);
            }
            float mu  = sum * (1.0f / 128.0f);
            float var = sq * (1.0f / 128.0f) - mu * mu;
            float rs  = rsqrtf(var + 1e-5f);
            int eg = e0 + r;
            if (eg < EDGES) {
                float* o = out + (size_t)eg * DIM;
                o[lane]      = (v0 - mu) * rs * g0 + be0;
                o[lane + 32] = (v1 - mu) * rs * g1 + be1;
                o[lane + 64] = (v2 - mu) * rs * g2 + be2;
                o[lane + 96] = (v3 - mu) * rs * g3 + be3;
            }
        }
    }
}

extern "C" void kernel_launch(void* const* d_in, const int* in_sizes, int n_in,
                              void* d_out, int out_size) {
    const float* node_attr = (const float*)d_in[0];
    const void*  eidx      = d_in[1];
    const float* edge_attr = (const float*)d_in[2];
    const float* W1        = (const float*)d_in[3];
    const float* b1        = (const float*)d_in[4];
    const float* W2        = (const float*)d_in[5];
    const float* b2        = (const float*)d_in[6];
    const float* gamma_    = (const float*)d_in[7];
    const float* beta_     = (const float*)d_in[8];

    int nblocks = (EDGES + BE - 1) / BE;  // 9766
    edge_mlp_kernel<<<nblocks, NT>>>(node_attr, eidx, edge_attr,
                                     W1, b1, W2, b2, gamma_, beta_,
                                     (float*)d_out);
}

// round 3
// speedup vs baseline: 3.7253x; 3.7253x over previous
#include <cuda_runtime.h>
#include <cstdint>

#define EDGES 625000
#define DD    128
#define BE    128
#define NT    256
#define NCTA  ((EDGES + BE - 1) / BE)   // 4883

// ---------------- smem layout (bytes) ----------------
#define SM_A    0          // A frag chunk: 32 blocks x 528B = 16896
#define SM_B    16896      // B frag chunk: 64 blocks x 256B = 16384
#define SM_H    33280      // H frag: 128 blocks x 512B = 65536
#define SM_P    98816      // params: b1,b2,gamma,beta (512B each), send,recv (512B each)
#define P_B1    (SM_P + 0)
#define P_B2    (SM_P + 512)
#define P_G     (SM_P + 1024)
#define P_BT    (SM_P + 1536)
#define P_SEND  (SM_P + 2048)
#define P_RECV  (SM_P + 2560)
#define SM_HOUT 0          // 128 x 132 floats = 67584 (overlays A/B/H-low, used post-GEMM2)
#define SMEM_ALLOC 102400

// weights in tf32 fragment layout: [kstep][ntile(16)][lane(32)][reg(2)]
__device__ float g_W1F[48 * 16 * 64];   // 49152
__device__ float g_W2F[16 * 16 * 64];   // 16384

__device__ __forceinline__ uint32_t f2tf32(float x) {
    uint32_t u;
    asm("cvt.rna.tf32.f32 %0, %1;" : "=r"(u) : "f"(x));
    return u;
}

// prep: W[k][n] row-major -> frag layout, tf32-rounded
__global__ void prep_w_kernel(const float* __restrict__ W1,
                              const float* __restrict__ W2) {
    int i = blockIdx.x * 256 + threadIdx.x;
    if (i < 384 * 128) {
        int k = i >> 7, n = i & 127;
        int ks = k >> 3, nt = n >> 3;
        int lane = (n & 7) * 4 + (k & 3);
        int reg  = (k & 7) >> 2;
        g_W1F[(ks * 16 + nt) * 64 + lane * 2 + reg] = __uint_as_float(f2tf32(W1[i]));
    }
    if (i < 128 * 128) {
        int k = i >> 7, n = i & 127;
        int ks = k >> 3, nt = n >> 3;
        int lane = (n & 7) * 4 + (k & 3);
        int reg  = (k & 7) >> 2;
        g_W2F[(ks * 16 + nt) * 64 + lane * 2 + reg] = __uint_as_float(f2tf32(W2[i]));
    }
}

__device__ __forceinline__ void mma_tf32(float& c0, float& c1, float& c2, float& c3,
                                         uint32_t a0, uint32_t a1, uint32_t a2, uint32_t a3,
                                         uint32_t b0, uint32_t b1) {
    asm volatile("mma.sync.aligned.m16n8k8.row.col.f32.tf32.tf32.f32 "
                 "{%0,%1,%2,%3}, {%4,%5,%6,%7}, {%8,%9}, {%0,%1,%2,%3};"
                 : "+f"(c0), "+f"(c1), "+f"(c2), "+f"(c3)
                 : "r"(a0), "r"(a1), "r"(a2), "r"(a3), "r"(b0), "r"(b1));
}

__global__ __launch_bounds__(NT, 1) void edge_mlp_mma(
    const float* __restrict__ node_attr,
    const void*  __restrict__ eidx_raw,
    const float* __restrict__ edge_attr,
    const float* __restrict__ b1g,
    const float* __restrict__ b2g,
    const float* __restrict__ gg,
    const float* __restrict__ btg,
    float* __restrict__ out)
{
    extern __shared__ char smem[];
    const int tid  = threadIdx.x;
    const int wid  = tid >> 5;
    const int lane = tid & 31;
    const int g    = lane >> 2;        // groupID
    const int t    = lane & 3;         // thread in group
    const int wm   = wid >> 2;         // 0..1 (M half)
    const int wn   = wid & 3;          // 0..3 (N quarter)
    const int e0   = blockIdx.x * BE;

    // ---- params + indices ----
    if (tid < 128) {
        ((float*)(smem + P_B1))[tid] = b1g[tid];
        ((float*)(smem + P_B2))[tid] = b2g[tid];
        ((float*)(smem + P_G ))[tid] = gg[tid];
        ((float*)(smem + P_BT))[tid] = btg[tid];
    }
    const int* raw32 = (const int*)eidx_raw;
    bool is64 = true;
    #pragma unroll
    for (int i = 0; i < 16; i++) is64 &= (raw32[2 * i + 1] == 0);
    if (tid < BE) {
        int eg = e0 + tid; if (eg >= EDGES) eg = EDGES - 1;
        int s, r;
        if (is64) { const long long* p = (const long long*)eidx_raw;
                    s = (int)p[eg]; r = (int)p[EDGES + eg]; }
        else      { s = raw32[eg]; r = raw32[EDGES + eg]; }
        ((int*)(smem + P_SEND))[tid] = s;
        ((int*)(smem + P_RECV))[tid] = r;
    }
    __syncthreads();

    const int* sSend = (const int*)(smem + P_SEND);
    const int* sRecv = (const int*)(smem + P_RECV);

    float acc[4][4][4];   // [mtile][ntile][reg]
    #pragma unroll
    for (int i = 0; i < 4; i++)
        #pragma unroll
        for (int j = 0; j < 4; j++)
            #pragma unroll
            for (int r = 0; r < 4; r++) acc[i][j][r] = 0.0f;

    float4 prA[4], prB[4];

    // prefetch chunk 0
    #pragma unroll
    for (int it = 0; it < 4; it++) {
        int idx = tid + it * NT;
        int row = idx >> 3, jc = idx & 7;
        prA[it] = *(const float4*)(node_attr + (size_t)sSend[row] * DD + jc * 4);
        prB[it] = *(const float4*)(g_W1F + idx * 4);
    }

    // =================== GEMM1: 12 chunks of k=32 ===================
    #pragma unroll 1
    for (int c = 0; c < 12; c++) {
        __syncthreads();
        // scatter A to frag layout (with tf32 rounding)
        #pragma unroll
        for (int it = 0; it < 4; it++) {
            int idx = tid + it * NT;
            int row = idx >> 3, jc = idx & 7;
            int bi  = (row >> 4) * 4 + (jc >> 1);
            int rbit = (row >> 3) & 1;
            uint32_t* dst = (uint32_t*)(smem + SM_A) + bi * 132 + (row & 7) * 16;
            const float* v = &prA[it].x;
            #pragma unroll
            for (int s4 = 0; s4 < 4; s4++)
                dst[s4 * 4 + rbit + 2 * (jc & 1)] = f2tf32(v[s4]);
            *(float4*)(smem + SM_B + idx * 16) = prB[it];
        }
        __syncthreads();

        // prefetch next chunk
        if (c < 11) {
            int cn = c + 1;
            #pragma unroll
            for (int it = 0; it < 4; it++) {
                int idx = tid + it * NT;
                int row = idx >> 3, jc = idx & 7;
                const float* src;
                if (cn < 4)      src = node_attr + (size_t)sSend[row] * DD + cn * 32;
                else if (cn < 8) src = node_attr + (size_t)sRecv[row] * DD + (cn - 4) * 32;
                else { int eg = e0 + row; if (eg >= EDGES) eg = EDGES - 1;
                       src = edge_attr + (size_t)eg * DD + (cn - 8) * 32; }
                prA[it] = *(const float4*)(src + jc * 4);
                prB[it] = *(const float4*)(g_W1F + cn * 4096 + idx * 4);
            }
        }

        // 4 k8-steps
        #pragma unroll
        for (int s = 0; s < 4; s++) {
            uint2 b[4];
            #pragma unroll
            for (int j = 0; j < 4; j++)
                b[j] = *(const uint2*)(smem + SM_B + ((s * 16) + wn * 4 + j) * 256 + lane * 8);
            #pragma unroll
            for (int i = 0; i < 4; i++) {
                uint4 a = *(const uint4*)(smem + SM_A + ((wm * 4 + i) * 4 + s) * 528 + lane * 16);
                #pragma unroll
                for (int j = 0; j < 4; j++)
                    mma_tf32(acc[i][j][0], acc[i][j][1], acc[i][j][2], acc[i][j][3],
                             a.x, a.y, a.z, a.w, b[j].x, b[j].y);
            }
        }
    }

    // prefetch GEMM2 B chunk 0 (overlap with epilogue1)
    #pragma unroll
    for (int it = 0; it < 4; it++) {
        int idx = tid + it * NT;
        prB[it] = *(const float4*)(g_W2F + idx * 4);
    }

    // ========== epilogue1: bias + ReLU + tf32, scatter to H frag ==========
    {
        const float* B1 = (const float*)(smem + P_B1);
        uint32_t* H = (uint32_t*)(smem + SM_H);
        #pragma unroll
        for (int i = 0; i < 4; i++) {
            int mt = wm * 4 + i;
            #pragma unroll
            for (int j = 0; j < 4; j++) {
                int ks2 = wn * 4 + j;
                int cbase = wn * 32 + j * 8;
                uint32_t* blk = H + (mt * 16 + ks2) * 128;
                #pragma unroll
                for (int r = 0; r < 4; r++) {
                    int col = cbase + 2 * t + (r & 1);
                    float x = acc[i][j][r] + B1[col];
                    x = fmaxf(x, 0.0f);
                    int kl = 2 * t + (r & 1);
                    int lane2 = g * 4 + (kl & 3);
                    int reg2  = (r >> 1) + 2 * ((kl >> 2) & 1);
                    blk[lane2 * 4 + reg2] = f2tf32(x);
                    acc[i][j][r] = 0.0f;   // reset for GEMM2
                }
            }
        }
    }

    // =================== GEMM2: 4 chunks of k=32 ===================
    #pragma unroll 1
    for (int c = 0; c < 4; c++) {
        __syncthreads();   // H frag complete (c=0) / B consumed (c>0)
        #pragma unroll
        for (int it = 0; it < 4; it++) {
            int idx = tid + it * NT;
            *(float4*)(smem + SM_B + idx * 16) = prB[it];
        }
        __syncthreads();
        if (c < 3) {
            #pragma unroll
            for (int it = 0; it < 4; it++) {
                int idx = tid + it * NT;
                prB[it] = *(const float4*)(g_W2F + (c + 1) * 4096 + idx * 4);
            }
        }
        #pragma unroll
        for (int s = 0; s < 4; s++) {
            uint2 b[4];
            #pragma unroll
            for (int j = 0; j < 4; j++)
                b[j] = *(const uint2*)(smem + SM_B + ((s * 16) + wn * 4 + j) * 256 + lane * 8);
            #pragma unroll
            for (int i = 0; i < 4; i++) {
                uint4 a = *(const uint4*)(smem + SM_H + ((wm * 4 + i) * 16 + (c * 4 + s)) * 512 + lane * 16);
                #pragma unroll
                for (int j = 0; j < 4; j++)
                    mma_tf32(acc[i][j][0], acc[i][j][1], acc[i][j][2], acc[i][j][3],
                             a.x, a.y, a.z, a.w, b[j].x, b[j].y);
            }
        }
    }

    __syncthreads();   // all GEMM2 frag reads done before Hout overwrites A/B/H-low

    // ========== epilogue2: bias2, store natural layout to Hout ==========
    {
        const float* B2 = (const float*)(smem + P_B2);
        float* Ho = (float*)(smem + SM_HOUT);
        #pragma unroll
        for (int i = 0; i < 4; i++) {
            int row0 = wm * 64 + i * 16 + g;
            #pragma unroll
            for (int j = 0; j < 4; j++) {
                int cbase = wn * 32 + j * 8 + 2 * t;
                #pragma unroll
                for (int r = 0; r < 4; r++) {
                    int row = row0 + ((r >> 1) << 3);
                    int col = cbase + (r & 1);
                    Ho[row * 132 + col] = acc[i][j][r] + B2[col];
                }
            }
        }
    }
    __syncthreads();

    // ========== LayerNorm + store ==========
    {
        const float* Ho = (const float*)(smem + SM_HOUT);
        const float* G  = (const float*)(smem + P_G);
        const float* Bt = (const float*)(smem + P_BT);
        float g0 = G[lane],      g1 = G[lane + 32],  g2 = G[lane + 64],  g3 = G[lane + 96];
        float b0 = Bt[lane],     b1 = Bt[lane + 32], b2 = Bt[lane + 64], b3 = Bt[lane + 96];
        #pragma unroll 1
        for (int k = 0; k < 16; k++) {
            int row = wid * 16 + k;
            float v0 = Ho[row * 132 + lane];
            float v1 = Ho[row * 132 + lane + 32];
            float v2 = Ho[row * 132 + lane + 64];
            float v3 = Ho[row * 132 + lane + 96];
            float sum = v0 + v1 + v2 + v3;
            float sq  = v0 * v0 + v1 * v1 + v2 * v2 + v3 * v3;
            #pragma unroll
            for (int off = 16; off > 0; off >>= 1) {
                sum += __shfl_xor_sync(0xffffffffu, sum, off);
                sq  += __shfl_xor_sync(0xffffffffu, sq,  off);
            }
            float mu  = sum * (1.0f / 128.0f);
            float var = sq * (1.0f / 128.0f) - mu * mu;
            float rs  = rsqrtf(var + 1e-5f);
            int eg = e0 + row;
            if (eg < EDGES) {
                float* o = out + (size_t)eg * DD;
                o[lane]      = (v0 - mu) * rs * g0 + b0;
                o[lane + 32] = (v1 - mu) * rs * g1 + b1;
                o[lane + 64] = (v2 - mu) * rs * g2 + b2;
                o[lane + 96] = (v3 - mu) * rs * g3 + b3;
            }
        }
    }
}

extern "C" void kernel_launch(void* const* d_in, const int* in_sizes, int n_in,
                              void* d_out, int out_size) {
    const float* node_attr = (const float*)d_in[0];
    const void*  eidx      = d_in[1];
    const float* edge_attr = (const float*)d_in[2];
    const float* W1        = (const float*)d_in[3];
    const float* b1        = (const float*)d_in[4];
    const float* W2        = (const float*)d_in[5];
    const float* b2        = (const float*)d_in[6];
    const float* gamma_    = (const float*)d_in[7];
    const float* beta_     = (const float*)d_in[8];

    cudaFuncSetAttribute(edge_mlp_mma, cudaFuncAttributeMaxDynamicSharedMemorySize, SMEM_ALLOC);

    prep_w_kernel<<<192, 256>>>(W1, W2);
    edge_mlp_mma<<<NCTA, NT, SMEM_ALLOC>>>(node_attr, eidx, edge_attr,
                                           b1, b2, gamma_, beta_, (float*)d_out);
}

// round 4
// speedup vs baseline: 3.9821x; 1.0689x over previous
#include <cuda_runtime.h>
#include <cstdint>

#define EDGES 625000
#define DD    128
#define BE    128
#define NT    512
#define NCTA  ((EDGES + BE - 1) / BE)   // 4883

// ---------------- smem layout (bytes) ----------------
// A frag buf: 64 blocks x 528B = 33792 ; x2
// B frag buf: 8 ksteps x 16 ntiles x 256B = 32768 ; x2
// H frag:     128 blocks x 528B = 67584
#define SM_A0   0
#define SM_A1   33792
#define SM_B0   67584
#define SM_B1   100352
#define SM_H    133120
#define SM_P    200704
#define P_B1    (SM_P + 0)
#define P_B2    (SM_P + 512)
#define P_G     (SM_P + 1024)
#define P_BT    (SM_P + 1536)
#define P_SEND  (SM_P + 2048)
#define P_RECV  (SM_P + 2560)
#define SM_HOUT 0                       // 128 x 132 f32 = 67584, overlays A0+A1 post-GEMM2
#define SMEM_ALLOC 204800

// weights in tf32 fragment layout: [kstep][ntile(16)][lane(32)][reg(2)]
__device__ __align__(16) float g_W1F[48 * 16 * 64];
__device__ __align__(16) float g_W2F[16 * 16 * 64];

__device__ __forceinline__ uint32_t f2tf32(float x) {
    uint32_t u;
    asm("cvt.rna.tf32.f32 %0, %1;" : "=r"(u) : "f"(x));
    return u;
}

__global__ void prep_w_kernel(const float* __restrict__ W1,
                              const float* __restrict__ W2) {
    int i = blockIdx.x * 256 + threadIdx.x;
    if (i < 384 * 128) {
        int k = i >> 7, n = i & 127;
        int ks = k >> 3, nt = n >> 3;
        int lane = (n & 7) * 4 + (k & 3);
        int reg  = (k & 7) >> 2;
        g_W1F[(ks * 16 + nt) * 64 + lane * 2 + reg] = __uint_as_float(f2tf32(W1[i]));
    }
    if (i < 128 * 128) {
        int k = i >> 7, n = i & 127;
        int ks = k >> 3, nt = n >> 3;
        int lane = (n & 7) * 4 + (k & 3);
        int reg  = (k & 7) >> 2;
        g_W2F[(ks * 16 + nt) * 64 + lane * 2 + reg] = __uint_as_float(f2tf32(W2[i]));
    }
}

__device__ __forceinline__ void mma_tf32(float& c0, float& c1, float& c2, float& c3,
                                         uint32_t a0, uint32_t a1, uint32_t a2, uint32_t a3,
                                         uint32_t b0, uint32_t b1) {
    asm volatile("mma.sync.aligned.m16n8k8.row.col.f32.tf32.tf32.f32 "
                 "{%0,%1,%2,%3}, {%4,%5,%6,%7}, {%8,%9}, {%0,%1,%2,%3};"
                 : "+f"(c0), "+f"(c1), "+f"(c2), "+f"(c3)
                 : "r"(a0), "r"(a1), "r"(a2), "r"(a3), "r"(b0), "r"(b1));
}

__device__ __forceinline__ void cp16(uint32_t saddr, const void* gptr) {
    asm volatile("cp.async.cg.shared.global [%0], [%1], 16;"
                 :: "r"(saddr), "l"(gptr));
}
#define CP_COMMIT() asm volatile("cp.async.commit_group;" ::: "memory")
#define CP_WAIT(n)  asm volatile("cp.async.wait_group %0;" :: "n"(n) : "memory")

__global__ __launch_bounds__(NT, 1) void edge_mlp_mma(
    const float* __restrict__ node_attr,
    const void*  __restrict__ eidx_raw,
    const float* __restrict__ edge_attr,
    const float* __restrict__ b1g,
    const float* __restrict__ b2g,
    const float* __restrict__ gg,
    const float* __restrict__ btg,
    float* __restrict__ out)
{
    extern __shared__ char smem[];
    uint32_t smb;
    asm("{ .reg .u64 t; cvta.to.shared.u64 t, %1; cvt.u32.u64 %0, t; }"
        : "=r"(smb) : "l"(smem));

    const int tid  = threadIdx.x;
    const int wid  = tid >> 5;
    const int lane = tid & 31;
    const int g    = lane >> 2;
    const int t    = lane & 3;
    const int wm   = wid >> 2;     // 0..3 (M quarter, 32 rows)
    const int wn   = wid & 3;      // 0..3 (N quarter, 32 cols)
    const int e0   = blockIdx.x * BE;

    if (tid < 128) {
        ((float*)(smem + P_B1))[tid] = b1g[tid];
        ((float*)(smem + P_B2))[tid] = b2g[tid];
        ((float*)(smem + P_G ))[tid] = gg[tid];
        ((float*)(smem + P_BT))[tid] = btg[tid];
    }
    const int* raw32 = (const int*)eidx_raw;
    bool is64 = true;
    #pragma unroll
    for (int i = 0; i < 16; i++) is64 &= (raw32[2 * i + 1] == 0);
    if (tid < BE) {
        int eg = e0 + tid; if (eg >= EDGES) eg = EDGES - 1;
        int s, r;
        if (is64) { const long long* p = (const long long*)eidx_raw;
                    s = (int)p[eg]; r = (int)p[EDGES + eg]; }
        else      { s = raw32[eg]; r = raw32[EDGES + eg]; }
        ((int*)(smem + P_SEND))[tid] = s;
        ((int*)(smem + P_RECV))[tid] = r;
    }
    __syncthreads();

    const int* sSend = (const int*)(smem + P_SEND);
    const int* sRecv = (const int*)(smem + P_RECV);
    const uint32_t bbuf[2] = {smb + SM_B0, smb + SM_B1};
    const uint32_t abufB[2] = {(uint32_t)SM_A0, (uint32_t)SM_A1};

    // issue B chunk 0 (GEMM1)
    #pragma unroll
    for (int it = 0; it < 4; it++) {
        int idx = tid + it * NT;               // 0..2047 (16B each = 32KB)
        cp16(bbuf[0] + idx * 16, g_W1F + idx * 4);
    }
    CP_COMMIT();

    // prefetch A chunk 0 (k = 0..63 of sender)
    float4 prA[4];
    #pragma unroll
    for (int it = 0; it < 4; it++) {
        int idx = tid + it * NT;               // 0..2047 float4 slots
        int row = idx >> 4, jc = idx & 15;
        prA[it] = *(const float4*)(node_attr + (size_t)sSend[row] * DD + jc * 4);
    }

    float acc[2][4][4];
    #pragma unroll
    for (int i = 0; i < 2; i++)
        #pragma unroll
        for (int j = 0; j < 4; j++)
            #pragma unroll
            for (int r = 0; r < 4; r++) acc[i][j][r] = 0.0f;

    // =================== GEMM1: 6 chunks of k=64 ===================
    #pragma unroll 1
    for (int c = 0; c < 6; c++) {
        const char* abuf = smem + abufB[c & 1];
        // scatter A(c) -> frag layout (tf32)
        #pragma unroll
        for (int it = 0; it < 4; it++) {
            int idx = tid + it * NT;
            int row = idx >> 4, jc = idx & 15;
            int blk  = (row >> 4) * 8 + (jc >> 1);
            int rbit = (row >> 3) & 1;
            int lo2  = 2 * (jc & 1);
            uint32_t* dst = (uint32_t*)(abuf + blk * 528) + (row & 7) * 16;
            const float* v = &prA[it].x;
            #pragma unroll
            for (int s4 = 0; s4 < 4; s4++)
                dst[s4 * 4 + lo2 + rbit] = f2tf32(v[s4]);
        }
        CP_WAIT(0);              // B(c) arrived
        __syncthreads();         // A(c) visible; MMA(c-1) done everywhere

        if (c < 5) {
            int cn = c + 1;
            #pragma unroll
            for (int it = 0; it < 4; it++) {
                int idx = tid + it * NT;
                cp16(bbuf[cn & 1] + idx * 16, g_W1F + cn * 8192 + idx * 4);
            }
            CP_COMMIT();
            #pragma unroll
            for (int it = 0; it < 4; it++) {
                int idx = tid + it * NT;
                int row = idx >> 4, jc = idx & 15;
                const float* src;
                if (cn < 2)      src = node_attr + (size_t)sSend[row] * DD + cn * 64;
                else if (cn < 4) src = node_attr + (size_t)sRecv[row] * DD + (cn - 2) * 64;
                else { int eg = e0 + row; if (eg >= EDGES) eg = EDGES - 1;
                       src = edge_attr + (size_t)eg * DD + (cn - 4) * 64; }
                prA[it] = *(const float4*)(src + jc * 4);
            }
        }

        const char* bb = smem + (SM_B0 + (c & 1) * 32768);
        #pragma unroll
        for (int s = 0; s < 8; s++) {
            uint2 b[4];
            #pragma unroll
            for (int j = 0; j < 4; j++)
                b[j] = *(const uint2*)(bb + ((s * 16) + wn * 4 + j) * 256 + lane * 8);
            #pragma unroll
            for (int i = 0; i < 2; i++) {
                uint4 a = *(const uint4*)(abuf + ((wm * 2 + i) * 8 + s) * 528 + lane * 16);
                #pragma unroll
                for (int j = 0; j < 4; j++)
                    mma_tf32(acc[i][j][0], acc[i][j][1], acc[i][j][2], acc[i][j][3],
                             a.x, a.y, a.z, a.w, b[j].x, b[j].y);
            }
        }
    }

    // issue GEMM2 B chunk 0 into buf0 (free: last read was MMA chunk4)
    #pragma unroll
    for (int it = 0; it < 4; it++) {
        int idx = tid + it * NT;
        cp16(bbuf[0] + idx * 16, g_W2F + idx * 4);
    }
    CP_COMMIT();

    // ========== epilogue1: bias + ReLU + tf32 -> H frag ==========
    {
        const float* B1 = (const float*)(smem + P_B1);
        #pragma unroll
        for (int i = 0; i < 2; i++) {
            int mtb = wm * 2 + i;
            #pragma unroll
            for (int j = 0; j < 4; j++) {
                int ks2 = wn * 4 + j;
                uint32_t* blkp = (uint32_t*)(smem + SM_H + (mtb * 16 + ks2) * 528);
                #pragma unroll
                for (int r = 0; r < 4; r++) {
                    int col = wn * 32 + j * 8 + 2 * t + (r & 1);
                    float x = fmaxf(acc[i][j][r] + B1[col], 0.0f);
                    int kl = 2 * t + (r & 1);
                    blkp[g * 16 + (kl & 3) * 4 + 2 * (kl >> 2) + (r >> 1)] = f2tf32(x);
                    acc[i][j][r] = 0.0f;
                }
            }
        }
    }
    __syncthreads();   // H complete; MMA1(5) done -> buf1 free

    // issue GEMM2 B chunk 1 into buf1
    #pragma unroll
    for (int it = 0; it < 4; it++) {
        int idx = tid + it * NT;
        cp16(bbuf[1] + idx * 16, g_W2F + 8192 + idx * 4);
    }
    CP_COMMIT();
    CP_WAIT(1);        // B2(0) done, B2(1) in flight
    __syncthreads();

    // =================== GEMM2: 2 chunks of k=64 ===================
    #pragma unroll 1
    for (int c = 0; c < 2; c++) {
        if (c == 1) { CP_WAIT(0); __syncthreads(); }
        const char* bb = smem + (SM_B0 + c * 32768);
        #pragma unroll
        for (int s = 0; s < 8; s++) {
            uint2 b[4];
            #pragma unroll
            for (int j = 0; j < 4; j++)
                b[j] = *(const uint2*)(bb + ((s * 16) + wn * 4 + j) * 256 + lane * 8);
            #pragma unroll
            for (int i = 0; i < 2; i++) {
                uint4 a = *(const uint4*)(smem + SM_H +
                          ((wm * 2 + i) * 16 + (c * 8 + s)) * 528 + lane * 16);
                #pragma unroll
                for (int j = 0; j < 4; j++)
                    mma_tf32(acc[i][j][0], acc[i][j][1], acc[i][j][2], acc[i][j][3],
                             a.x, a.y, a.z, a.w, b[j].x, b[j].y);
            }
        }
    }
    __syncthreads();   // all GEMM2 reads done before Hout overlays A buffers

    // ========== epilogue2: bias2 -> Hout (natural layout) ==========
    {
        const float* B2 = (const float*)(smem + P_B2);
        float* Ho = (float*)(smem + SM_HOUT);
        #pragma unroll
        for (int i = 0; i < 2; i++) {
            #pragma unroll
            for (int j = 0; j < 4; j++) {
                #pragma unroll
                for (int r = 0; r < 4; r++) {
                    int row = wm * 32 + i * 16 + g + 8 * (r >> 1);
                    int col = wn * 32 + j * 8 + 2 * t + (r & 1);
                    Ho[row * 132 + col] = acc[i][j][r] + B2[col];
                }
            }
        }
    }
    __syncthreads();

    // ========== LayerNorm + store ==========
    {
        const float* Ho = (const float*)(smem + SM_HOUT);
        const float* G  = (const float*)(smem + P_G);
        const float* Bt = (const float*)(smem + P_BT);
        float g0 = G[lane],      g1 = G[lane + 32],  g2 = G[lane + 64],  g3 = G[lane + 96];
        float b0 = Bt[lane],     b1 = Bt[lane + 32], b2 = Bt[lane + 64], b3 = Bt[lane + 96];
        #pragma unroll 1
        for (int k = 0; k < 8; k++) {
            int row = wid * 8 + k;
            float v0 = Ho[row * 132 + lane];
            float v1 = Ho[row * 132 + lane + 32];
            float v2 = Ho[row * 132 + lane + 64];
            float v3 = Ho[row * 132 + lane + 96];
            float sum = v0 + v1 + v2 + v3;
            float sq  = v0 * v0 + v1 * v1 + v2 * v2 + v3 * v3;
            #pragma unroll
            for (int off = 16; off > 0; off >>= 1) {
                sum += __shfl_xor_sync(0xffffffffu, sum, off);
                sq  += __shfl_xor_sync(0xffffffffu, sq,  off);
            }
            float mu  = sum * (1.0f / 128.0f);
            float var = sq * (1.0f / 128.0f) - mu * mu;
            float rs  = rsqrtf(var + 1e-5f);
            int eg = e0 + row;
            if (eg < EDGES) {
                float* o = out + (size_t)eg * DD;
                o[lane]      = (v0 - mu) * rs * g0 + b0;
                o[lane + 32] = (v1 - mu) * rs * g1 + b1;
                o[lane + 64] = (v2 - mu) * rs * g2 + b2;
                o[lane + 96] = (v3 - mu) * rs * g3 + b3;
            }
        }
    }
}

extern "C" void kernel_launch(void* const* d_in, const int* in_sizes, int n_in,
                              void* d_out, int out_size) {
    const float* node_attr = (const float*)d_in[0];
    const void*  eidx      = d_in[1];
    const float* edge_attr = (const float*)d_in[2];
    const float* W1        = (const float*)d_in[3];
    const float* b1        = (const float*)d_in[4];
    const float* W2        = (const float*)d_in[5];
    const float* b2        = (const float*)d_in[6];
    const float* gamma_    = (const float*)d_in[7];
    const float* beta_     = (const float*)d_in[8];

    cudaFuncSetAttribute(edge_mlp_mma, cudaFuncAttributeMaxDynamicSharedMemorySize, SMEM_ALLOC);

    prep_w_kernel<<<192, 256>>>(W1, W2);
    edge_mlp_mma<<<NCTA, NT, SMEM_ALLOC>>>(node_attr, eidx, edge_attr,
                                           b1, b2, gamma_, beta_, (float*)d_out);
}